// round 15
// baseline (speedup 1.0000x reference)
#include <cuda_runtime.h>
#include <math.h>
#include <stdint.h>

// Problem constants (fixed by the dataset)
#define T_TYPES 4
#define U_DIM   10
#define U_PAD   12                     // agg row stride: 48 floats, 16B-aligned rows
#define EMB     200
#define DIM_A   20
#define TUP     (T_TYPES * U_PAD)      // 48 floats per dst node
#define TU_RAW  (T_TYPES * U_DIM)      // 40 floats per nte row
#define MAX_NDST 8192
#define NSLICE  7                      // ceil(EMB/32)
#define PROWS   16                     // rows per project block (all 4 t's)
#define SLOT_F  224                    // floats per ring slot (200 base + 12 comb + pad)
#define RING    4                      // ring depth
#define NCHUNK  53                     // 16B chunks per row (50 base + 3 comb)
#define KREP    4                      // accumulator replicas (breaks per-address serialization)
#define REP_STRIDE (MAX_NDST * TUP)

// Scratch (device globals: allocation-free; zero-initialized at load)
__device__ float g_agg[KREP * REP_STRIDE];     // 4 replicas; re-zeroed by combine
__device__ float g_comb12[MAX_NDST * 12];      // [b][u], padded to 48B rows
__device__ float g_base[MAX_NDST * EMB];       // staged base rows, 6.5 MB (L2-resident)

// ---------------------------------------------------------------------------
// cp.async helpers
// ---------------------------------------------------------------------------
__device__ __forceinline__ void cp16(uint32_t dst_smem, const float* src) {
    asm volatile("cp.async.cg.shared.global [%0], [%1], 16;\n"
                 :: "r"(dst_smem), "l"(src));
}
__device__ __forceinline__ void cp_commit() {
    asm volatile("cp.async.commit_group;\n" ::: "memory");
}
template <int N>
__device__ __forceinline__ void cp_wait() {
    asm volatile("cp.async.wait_group %0;\n" :: "n"(N) : "memory");
}

// ---------------------------------------------------------------------------
// K1: per-edge scatter-add into REPLICATED accumulators.
//     4 edges per thread.  Trailing blocks stage base rows.
// ---------------------------------------------------------------------------
__device__ __forceinline__ void red_v4(float* p, float4 v) {
    asm volatile("red.global.add.v4.f32 [%0], {%1, %2, %3, %4};"
                 :: "l"(p), "f"(v.x), "f"(v.y), "f"(v.z), "f"(v.w)
                 : "memory");
}
__device__ __forceinline__ void red_v2(float* p, float2 v) {
    asm volatile("red.global.add.v2.f32 [%0], {%1, %2};"
                 :: "l"(p), "f"(v.x), "f"(v.y)
                 : "memory");
}

__global__ void edge_kernel(const int* __restrict__ edge_src,
                            const int* __restrict__ edge_dst,
                            const int* __restrict__ input_nodes,
                            const int* __restrict__ output_nodes,
                            const float* __restrict__ nte_table,
                            const float* __restrict__ node_emb,
                            int E, int quads_per_t, int edge_total,
                            int n_dst) {
    int idx = blockIdx.x * blockDim.x + threadIdx.x;

    if (idx < edge_total) {
        int t = idx / quads_per_t;
        int e = (idx - t * quads_per_t) << 2;

        const int4 ss = __ldg(reinterpret_cast<const int4*>(edge_src + (size_t)t * E + e));
        const int4 dd = __ldg(reinterpret_cast<const int4*>(edge_dst + (size_t)t * E + e));
        int s[4] = {ss.x, ss.y, ss.z, ss.w};
        int d[4] = {dd.x, dd.y, dd.z, dd.w};

        int node[4];
#pragma unroll
        for (int k = 0; k < 4; k++) node[k] = __ldg(&input_nodes[s[k]]);

        float2 r[4][5];
#pragma unroll
        for (int k = 0; k < 4; k++) {
            const float2* p = reinterpret_cast<const float2*>(
                nte_table + (size_t)node[k] * TU_RAW + t * U_DIM);
#pragma unroll
            for (int q = 0; q < 5; q++) r[k][q] = __ldg(&p[q]);
        }

        // replica: decorrelate neighbors so per-address chains shrink 4x
        float* agg_rep = g_agg + (size_t)(idx & (KREP - 1)) * REP_STRIDE;
#pragma unroll
        for (int k = 0; k < 4; k++) {
            float* dst = agg_rep + (size_t)d[k] * TUP + t * U_PAD;   // 16B-aligned
            red_v4(dst,     make_float4(r[k][0].x, r[k][0].y, r[k][1].x, r[k][1].y));
            red_v4(dst + 4, make_float4(r[k][2].x, r[k][2].y, r[k][3].x, r[k][3].y));
            red_v2(dst + 8, r[k][4]);
        }
    } else {
        // base-row staging (independent of edges, overlaps atomics)
        int j = idx - edge_total;
        int n_stage = n_dst * (EMB / 4);       // 50 float4 per row
        if (j < n_stage) {
            int b = j / (EMB / 4);
            int q = j - b * (EMB / 4);
            int node = __ldg(&output_nodes[b]);
            reinterpret_cast<float4*>(g_base + (size_t)b * EMB)[q] =
                __ldg(reinterpret_cast<const float4*>(node_emb + (size_t)node * EMB) + q);
        }
    }
}

// ---------------------------------------------------------------------------
// K2: attention + combine + RE-ZERO all agg replicas.  FOUR lanes per node.
//     (replicas start zeroed at module load; each call leaves them zeroed.)
// ---------------------------------------------------------------------------
__global__ void __launch_bounds__(256)
combine_kernel(const float* __restrict__ s1,    // [T,U,A]
               const float* __restrict__ s2,    // [T,A,1]
               int n_dst)
{
    __shared__ float s1_s[T_TYPES * U_DIM * DIM_A];
    __shared__ float s2_s[T_TYPES * DIM_A];

    int tid = threadIdx.x;
    for (int i = tid; i < T_TYPES * U_DIM * DIM_A; i += 256) s1_s[i] = __ldg(&s1[i]);
    if (tid < T_TYPES * DIM_A) s2_s[tid] = __ldg(&s2[tid]);
    __syncthreads();

    int gidx = blockIdx.x * blockDim.x + tid;
    int j = gidx >> 2;          // node
    int t = gidx & 3;           // edge type
    if (j >= n_dst) return;

    // sum the KREP replica rows (batched loads), then re-zero them
    float nte[12];
    {
        float4 acc[3];
        float4 ld[KREP][3];
#pragma unroll
        for (int rp = 0; rp < KREP; rp++) {
            const float4* p = reinterpret_cast<const float4*>(
                g_agg + (size_t)rp * REP_STRIDE + (size_t)j * TUP + t * U_PAD);
#pragma unroll
            for (int q = 0; q < 3; q++) ld[rp][q] = p[q];
        }
#pragma unroll
        for (int q = 0; q < 3; q++) {
            acc[q] = ld[0][q];
#pragma unroll
            for (int rp = 1; rp < KREP; rp++) {
                acc[q].x += ld[rp][q].x; acc[q].y += ld[rp][q].y;
                acc[q].z += ld[rp][q].z; acc[q].w += ld[rp][q].w;
            }
        }
        float4 z = make_float4(0.f, 0.f, 0.f, 0.f);
#pragma unroll
        for (int rp = 0; rp < KREP; rp++) {
            float4* p = reinterpret_cast<float4*>(
                g_agg + (size_t)rp * REP_STRIDE + (size_t)j * TUP + t * U_PAD);
            p[0] = z; p[1] = z; p[2] = z;
        }
#pragma unroll
        for (int q = 0; q < 3; q++) {
            nte[4 * q] = acc[q].x; nte[4 * q + 1] = acc[q].y;
            nte[4 * q + 2] = acc[q].z; nte[4 * q + 3] = acc[q].w;
        }
    }

    float score = 0.0f;
#pragma unroll
    for (int a = 0; a < DIM_A; a++) {
        float h = 0.0f;
#pragma unroll
        for (int u = 0; u < U_DIM; u++)
            h += nte[u] * s1_s[(t * U_DIM + u) * DIM_A + a];
        score += tanhf(h) * s2_s[t * DIM_A + a];
    }

    float m = score;
    m = fmaxf(m, __shfl_xor_sync(0xffffffffu, m, 1));
    m = fmaxf(m, __shfl_xor_sync(0xffffffffu, m, 2));
    float ex = expf(score - m);
    float sum = ex;
    sum += __shfl_xor_sync(0xffffffffu, sum, 1);
    sum += __shfl_xor_sync(0xffffffffu, sum, 2);
    float att = ex / sum;

    float comb[U_DIM];
#pragma unroll
    for (int u = 0; u < U_DIM; u++) {
        float v = att * nte[u];
        v += __shfl_xor_sync(0xffffffffu, v, 1);
        v += __shfl_xor_sync(0xffffffffu, v, 2);
        comb[u] = v;
    }
    if (t == 0) {
        float4* o = reinterpret_cast<float4*>(g_comb12 + (size_t)j * 12);
        o[0] = make_float4(comb[0], comb[1], comb[2], comb[3]);
        o[1] = make_float4(comb[4], comb[5], comb[6], comb[7]);
        o[2] = make_float4(comb[8], comb[9], 0.0f, 0.0f);
    }
}

// ---------------------------------------------------------------------------
// K3: projection + normalize.  Block = 4 warps = 4 edge types sharing ONE
//     cp.async ring.  Warp w owns t=w with W[t] in 70 regs.
// ---------------------------------------------------------------------------
__device__ __forceinline__ void prefetch_row(float* slotp, int b, int lane) {
    const float* base_g = g_base + (size_t)b * EMB;
    const float* comb_g = g_comb12 + (size_t)b * 12;
    uint32_t slot_addr = (uint32_t)__cvta_generic_to_shared(slotp);
    {
        int ch = lane;                          // < 53 always
        const float* src = (ch < 50) ? (base_g + ch * 4) : (comb_g + (ch - 50) * 4);
        cp16(slot_addr + ch * 16, src);
    }
    {
        int ch = lane + 32;                     // lanes 0..20 only
        if (ch < NCHUNK) {
            const float* src = (ch < 50) ? (base_g + ch * 4) : (comb_g + (ch - 50) * 4);
            cp16(slot_addr + ch * 16, src);
        }
    }
}

__global__ void __launch_bounds__(128)
project_kernel(const float* __restrict__ W,      // [T,U,EMB]
               float* __restrict__ out,          // [B,T,EMB]
               int n_dst)
{
    __shared__ float sbuf[RING * SLOT_F];        // 4 slots x 224 f = 3.6 KB

    int lane = threadIdx.x & 31;
    int w    = threadIdx.x >> 5;                 // warp == edge type t
    int t    = w;
    int b0   = blockIdx.x * PROWS;

    float Wr[NSLICE][U_DIM];
#pragma unroll
    for (int it = 0; it < NSLICE; it++) {
        int e = it * 32 + lane;
#pragma unroll
        for (int u = 0; u < U_DIM; u++)
            Wr[it][u] = (e < EMB) ? __ldg(&W[(size_t)(t * U_DIM + u) * EMB + e]) : 0.0f;
    }

    int bmax = n_dst - 1;
    if (w == 0) {
#pragma unroll
        for (int r = 0; r < 3; r++) {
            int bb = b0 + r; if (bb > bmax) bb = bmax;
            prefetch_row(&sbuf[r * SLOT_F], bb, lane);
            cp_commit();
        }
        cp_wait<2>();                            // row 0 landed
    }
    __syncthreads();

#pragma unroll 4
    for (int r = 0; r < PROWS; r++) {
        if (w == 0) {
            int rn = r + 3;
            if (rn < PROWS) {
                int bb = b0 + rn; if (bb > bmax) bb = bmax;
                prefetch_row(&sbuf[(rn & 3) * SLOT_F], bb, lane);
            }
            cp_commit();
        }

        float* slotp = &sbuf[(r & 3) * SLOT_F];
        int b = b0 + r;
        if (b < n_dst) {
            float c[U_DIM];
#pragma unroll
            for (int u = 0; u < U_DIM; u++) c[u] = slotp[EMB + u];

            float v[NSLICE];
            float ssq = 0.0f;
#pragma unroll
            for (int it = 0; it < NSLICE; it++) {
                int e = it * 32 + lane;
                float val = (e < EMB) ? slotp[e] : 0.0f;
#pragma unroll
                for (int u = 0; u < U_DIM; u++)
                    val += c[u] * Wr[it][u];
                v[it] = val;
                ssq += val * val;
            }
#pragma unroll
            for (int off = 16; off > 0; off >>= 1)
                ssq += __shfl_xor_sync(0xffffffffu, ssq, off);
            float inv = rsqrtf(fmaxf(ssq, 1e-24f));

            float* o = out + ((size_t)b * T_TYPES + t) * EMB;
#pragma unroll
            for (int it = 0; it < NSLICE; it++) {
                int e = it * 32 + lane;
                if (e < EMB) o[e] = v[it] * inv;
            }
        }

        if (w == 0) cp_wait<2>();
        __syncthreads();
    }
}

// ---------------------------------------------------------------------------
// Launch
// ---------------------------------------------------------------------------
extern "C" void kernel_launch(void* const* d_in, const int* in_sizes, int n_in,
                              void* d_out, int out_size) {
    const int*   input_nodes  = (const int*)  d_in[0];
    const int*   output_nodes = (const int*)  d_in[1];
    const int*   edge_src     = (const int*)  d_in[2];
    const int*   edge_dst     = (const int*)  d_in[3];
    const float* node_emb     = (const float*)d_in[4];
    const float* nte_table    = (const float*)d_in[5];
    const float* W            = (const float*)d_in[6];
    const float* s1           = (const float*)d_in[7];
    const float* s2           = (const float*)d_in[8];
    float* out = (float*)d_out;

    int n_dst = in_sizes[1];
    int E     = in_sizes[2] / T_TYPES;

    // K1: edge scatter-add (replicated accumulators) + base staging
    {
        int quads      = E >> 2;
        int edge_total = T_TYPES * quads;
        int n_stage    = n_dst * (EMB / 4);
        int nthreads   = edge_total + n_stage;
        edge_kernel<<<(nthreads + 255) / 256, 256>>>(
            edge_src, edge_dst, input_nodes, output_nodes,
            nte_table, node_emb, E, quads, edge_total, n_dst);
    }
    // K2: attention + combine + re-zero replicas (4 lanes per node)
    {
        int n = n_dst * T_TYPES;
        combine_kernel<<<(n + 255) / 256, 256>>>(s1, s2, n_dst);
    }
    // K3: projection + normalize (shared ring, 4 t's per block)
    {
        dim3 grid((n_dst + PROWS - 1) / PROWS);
        project_kernel<<<grid, 128>>>(W, out, n_dst);
    }
}

// round 16
// speedup vs baseline: 1.0343x; 1.0343x over previous
#include <cuda_runtime.h>
#include <math.h>
#include <stdint.h>

// Problem constants (fixed by the dataset)
#define T_TYPES 4
#define U_DIM   10
#define U_PAD   12                     // agg row stride: 48 floats, 16B-aligned rows
#define EMB     200
#define DIM_A   20
#define TUP     (T_TYPES * U_PAD)      // 48 floats per dst node
#define TU_RAW  (T_TYPES * U_DIM)      // 40 floats per nte row
#define MAX_NDST 8192
#define NSLICE  7                      // ceil(EMB/32)
#define PROWS   16                     // rows per project block (all 4 t's)
#define SLOT_F  224                    // floats per ring slot (200 base + 12 comb + pad)
#define RING    4                      // ring depth
#define NCHUNK  53                     // 16B chunks per row (50 base + 3 comb)

// Scratch (device globals: allocation-free; zero-initialized at load)
__device__ float g_agg[MAX_NDST * TUP];        // re-zeroed by combine each call
__device__ float g_comb12[MAX_NDST * 12];      // [b][u], padded to 48B rows
__device__ float g_base[MAX_NDST * EMB];       // staged base rows, 6.5 MB (L2-resident)

// ---------------------------------------------------------------------------
// cp.async helpers
// ---------------------------------------------------------------------------
__device__ __forceinline__ void cp16(uint32_t dst_smem, const float* src) {
    asm volatile("cp.async.cg.shared.global [%0], [%1], 16;\n"
                 :: "r"(dst_smem), "l"(src));
}
__device__ __forceinline__ void cp_commit() {
    asm volatile("cp.async.commit_group;\n" ::: "memory");
}
template <int N>
__device__ __forceinline__ void cp_wait() {
    asm volatile("cp.async.wait_group %0;\n" :: "n"(N) : "memory");
}

// ---------------------------------------------------------------------------
// K1: per-edge scatter-add ONLY (all non-edge traffic evicted — this kernel
//     is LTS-sector-throughput bound; every byte here costs wall time).
// ---------------------------------------------------------------------------
__device__ __forceinline__ void red_v4(float* p, float4 v) {
    asm volatile("red.global.add.v4.f32 [%0], {%1, %2, %3, %4};"
                 :: "l"(p), "f"(v.x), "f"(v.y), "f"(v.z), "f"(v.w)
                 : "memory");
}
__device__ __forceinline__ void red_v2(float* p, float2 v) {
    asm volatile("red.global.add.v2.f32 [%0], {%1, %2};"
                 :: "l"(p), "f"(v.x), "f"(v.y)
                 : "memory");
}

__global__ void edge_kernel(const int* __restrict__ edge_src,
                            const int* __restrict__ edge_dst,
                            const int* __restrict__ input_nodes,
                            const float* __restrict__ nte_table,
                            int E, int quads_per_t) {
    int idx = blockIdx.x * blockDim.x + threadIdx.x;
    int total = T_TYPES * quads_per_t;
    if (idx >= total) return;

    int t = idx / quads_per_t;
    int e = (idx - t * quads_per_t) << 2;

    const int4 ss = __ldg(reinterpret_cast<const int4*>(edge_src + (size_t)t * E + e));
    const int4 dd = __ldg(reinterpret_cast<const int4*>(edge_dst + (size_t)t * E + e));
    int s[4] = {ss.x, ss.y, ss.z, ss.w};
    int d[4] = {dd.x, dd.y, dd.z, dd.w};

    int node[4];
#pragma unroll
    for (int k = 0; k < 4; k++) node[k] = __ldg(&input_nodes[s[k]]);

    float2 r[4][5];
#pragma unroll
    for (int k = 0; k < 4; k++) {
        const float2* p = reinterpret_cast<const float2*>(
            nte_table + (size_t)node[k] * TU_RAW + t * U_DIM);
#pragma unroll
        for (int q = 0; q < 5; q++) r[k][q] = __ldg(&p[q]);
    }
#pragma unroll
    for (int k = 0; k < 4; k++) {
        float* dst = g_agg + (size_t)d[k] * TUP + t * U_PAD;   // 16B-aligned
        red_v4(dst,     make_float4(r[k][0].x, r[k][0].y, r[k][1].x, r[k][1].y));
        red_v4(dst + 4, make_float4(r[k][2].x, r[k][2].y, r[k][3].x, r[k][3].y));
        red_v2(dst + 8, r[k][4]);
    }
}

// ---------------------------------------------------------------------------
// K2: attention + combine + RE-ZERO g_agg  (leading blocks)
//     + base-row staging (trailing blocks — moved out of the L2-bound edge
//       kernel; pure MLP gather rides here nearly free).
// ---------------------------------------------------------------------------
__global__ void __launch_bounds__(256)
combine_kernel(const float* __restrict__ s1,    // [T,U,A]
               const float* __restrict__ s2,    // [T,A,1]
               const int*   __restrict__ output_nodes,
               const float* __restrict__ node_emb,
               int n_dst, int comb_total)
{
    int gidx = blockIdx.x * blockDim.x + threadIdx.x;

    if (gidx >= comb_total) {
        // ---- base-row staging ----
        int j = gidx - comb_total;
        int n_stage = n_dst * (EMB / 4);       // 50 float4 per row
        if (j < n_stage) {
            int b = j / (EMB / 4);
            int q = j - b * (EMB / 4);
            int node = __ldg(&output_nodes[b]);
            reinterpret_cast<float4*>(g_base + (size_t)b * EMB)[q] =
                __ldg(reinterpret_cast<const float4*>(node_emb + (size_t)node * EMB) + q);
        }
        return;
    }

    __shared__ float s1_s[T_TYPES * U_DIM * DIM_A];
    __shared__ float s2_s[T_TYPES * DIM_A];

    int tid = threadIdx.x;
    for (int i = tid; i < T_TYPES * U_DIM * DIM_A; i += 256) s1_s[i] = __ldg(&s1[i]);
    if (tid < T_TYPES * DIM_A) s2_s[tid] = __ldg(&s2[tid]);
    __syncthreads();

    int j = gidx >> 2;          // node
    int t = gidx & 3;           // edge type
    if (j >= n_dst) return;

    float nte[12];
    {
        float4* p = reinterpret_cast<float4*>(
            g_agg + (size_t)j * TUP + t * U_PAD);
#pragma unroll
        for (int q = 0; q < 3; q++) {
            float4 v = p[q];
            nte[4 * q] = v.x; nte[4 * q + 1] = v.y;
            nte[4 * q + 2] = v.z; nte[4 * q + 3] = v.w;
        }
        // re-zero this row for the next call (read-then-write, same thread)
        float4 z = make_float4(0.f, 0.f, 0.f, 0.f);
        p[0] = z; p[1] = z; p[2] = z;
    }

    float score = 0.0f;
#pragma unroll
    for (int a = 0; a < DIM_A; a++) {
        float h = 0.0f;
#pragma unroll
        for (int u = 0; u < U_DIM; u++)
            h += nte[u] * s1_s[(t * U_DIM + u) * DIM_A + a];
        score += tanhf(h) * s2_s[t * DIM_A + a];
    }

    float m = score;
    m = fmaxf(m, __shfl_xor_sync(0xffffffffu, m, 1));
    m = fmaxf(m, __shfl_xor_sync(0xffffffffu, m, 2));
    float ex = expf(score - m);
    float sum = ex;
    sum += __shfl_xor_sync(0xffffffffu, sum, 1);
    sum += __shfl_xor_sync(0xffffffffu, sum, 2);
    float att = ex / sum;

    float comb[U_DIM];
#pragma unroll
    for (int u = 0; u < U_DIM; u++) {
        float v = att * nte[u];
        v += __shfl_xor_sync(0xffffffffu, v, 1);
        v += __shfl_xor_sync(0xffffffffu, v, 2);
        comb[u] = v;
    }
    if (t == 0) {
        float4* o = reinterpret_cast<float4*>(g_comb12 + (size_t)j * 12);
        o[0] = make_float4(comb[0], comb[1], comb[2], comb[3]);
        o[1] = make_float4(comb[4], comb[5], comb[6], comb[7]);
        o[2] = make_float4(comb[8], comb[9], 0.0f, 0.0f);
    }
}

// ---------------------------------------------------------------------------
// K3: projection + normalize.  Block = 4 warps = 4 edge types sharing ONE
//     cp.async ring.  Warp w owns t=w with W[t] in 70 regs.
// ---------------------------------------------------------------------------
__device__ __forceinline__ void prefetch_row(float* slotp, int b, int lane) {
    const float* base_g = g_base + (size_t)b * EMB;
    const float* comb_g = g_comb12 + (size_t)b * 12;
    uint32_t slot_addr = (uint32_t)__cvta_generic_to_shared(slotp);
    {
        int ch = lane;                          // < 53 always
        const float* src = (ch < 50) ? (base_g + ch * 4) : (comb_g + (ch - 50) * 4);
        cp16(slot_addr + ch * 16, src);
    }
    {
        int ch = lane + 32;                     // lanes 0..20 only
        if (ch < NCHUNK) {
            const float* src = (ch < 50) ? (base_g + ch * 4) : (comb_g + (ch - 50) * 4);
            cp16(slot_addr + ch * 16, src);
        }
    }
}

__global__ void __launch_bounds__(128)
project_kernel(const float* __restrict__ W,      // [T,U,EMB]
               float* __restrict__ out,          // [B,T,EMB]
               int n_dst)
{
    __shared__ float sbuf[RING * SLOT_F];        // 4 slots x 224 f = 3.6 KB

    int lane = threadIdx.x & 31;
    int w    = threadIdx.x >> 5;                 // warp == edge type t
    int t    = w;
    int b0   = blockIdx.x * PROWS;

    float Wr[NSLICE][U_DIM];
#pragma unroll
    for (int it = 0; it < NSLICE; it++) {
        int e = it * 32 + lane;
#pragma unroll
        for (int u = 0; u < U_DIM; u++)
            Wr[it][u] = (e < EMB) ? __ldg(&W[(size_t)(t * U_DIM + u) * EMB + e]) : 0.0f;
    }

    int bmax = n_dst - 1;
    if (w == 0) {
#pragma unroll
        for (int r = 0; r < 3; r++) {
            int bb = b0 + r; if (bb > bmax) bb = bmax;
            prefetch_row(&sbuf[r * SLOT_F], bb, lane);
            cp_commit();
        }
        cp_wait<2>();                            // row 0 landed
    }
    __syncthreads();

#pragma unroll 4
    for (int r = 0; r < PROWS; r++) {
        if (w == 0) {
            int rn = r + 3;
            if (rn < PROWS) {
                int bb = b0 + rn; if (bb > bmax) bb = bmax;
                prefetch_row(&sbuf[(rn & 3) * SLOT_F], bb, lane);
            }
            cp_commit();
        }

        float* slotp = &sbuf[(r & 3) * SLOT_F];
        int b = b0 + r;
        if (b < n_dst) {
            float c[U_DIM];
#pragma unroll
            for (int u = 0; u < U_DIM; u++) c[u] = slotp[EMB + u];

            float v[NSLICE];
            float ssq = 0.0f;
#pragma unroll
            for (int it = 0; it < NSLICE; it++) {
                int e = it * 32 + lane;
                float val = (e < EMB) ? slotp[e] : 0.0f;
#pragma unroll
                for (int u = 0; u < U_DIM; u++)
                    val += c[u] * Wr[it][u];
                v[it] = val;
                ssq += val * val;
            }
#pragma unroll
            for (int off = 16; off > 0; off >>= 1)
                ssq += __shfl_xor_sync(0xffffffffu, ssq, off);
            float inv = rsqrtf(fmaxf(ssq, 1e-24f));

            float* o = out + ((size_t)b * T_TYPES + t) * EMB;
#pragma unroll
            for (int it = 0; it < NSLICE; it++) {
                int e = it * 32 + lane;
                if (e < EMB) o[e] = v[it] * inv;
            }
        }

        if (w == 0) cp_wait<2>();
        __syncthreads();
    }
}

// ---------------------------------------------------------------------------
// Launch
// ---------------------------------------------------------------------------
extern "C" void kernel_launch(void* const* d_in, const int* in_sizes, int n_in,
                              void* d_out, int out_size) {
    const int*   input_nodes  = (const int*)  d_in[0];
    const int*   output_nodes = (const int*)  d_in[1];
    const int*   edge_src     = (const int*)  d_in[2];
    const int*   edge_dst     = (const int*)  d_in[3];
    const float* node_emb     = (const float*)d_in[4];
    const float* nte_table    = (const float*)d_in[5];
    const float* W            = (const float*)d_in[6];
    const float* s1           = (const float*)d_in[7];
    const float* s2           = (const float*)d_in[8];
    float* out = (float*)d_out;

    int n_dst = in_sizes[1];
    int E     = in_sizes[2] / T_TYPES;

    // K1: edge scatter-add only (the LTS-bound kernel carries nothing else)
    {
        int quads = E >> 2;
        int n = T_TYPES * quads;
        edge_kernel<<<(n + 255) / 256, 256>>>(
            edge_src, edge_dst, input_nodes, nte_table, E, quads);
    }
    // K2: attention + combine + re-zero agg, with base staging in trailing blocks
    {
        int comb_total = n_dst * T_TYPES;                 // 32768
        int n_stage    = n_dst * (EMB / 4);               // 409600
        int nthreads   = comb_total + n_stage;
        combine_kernel<<<(nthreads + 255) / 256, 256>>>(
            s1, s2, output_nodes, node_emb, n_dst, comb_total);
    }
    // K3: projection + normalize (shared ring, 4 t's per block)
    {
        dim3 grid((n_dst + PROWS - 1) / PROWS);
        project_kernel<<<grid, 128>>>(W, out, n_dst);
    }
}